// round 14
// baseline (speedup 1.0000x reference)
#include <cuda_runtime.h>
#include <math.h>
#include <stdint.h>

#define B_  128
#define T_  1024
#define NX_ 256
#define NH_ 512
#define NY_ 256

// Progress flags: g_flag2[bt][group][jt], row padded to 32 words (128B).
__device__ unsigned g_flag2[16][2][32];

// ---------------------------------------------------------------------------
// FFMA2 helpers
// ---------------------------------------------------------------------------
__device__ __forceinline__ void ffma2(unsigned long long& d,
                                      unsigned long long a, unsigned long long b)
{
    asm("fma.rn.f32x2 %0, %1, %2, %0;" : "+l"(d) : "l"(a), "l"(b));
}
__device__ __forceinline__ unsigned long long pack2(float x)
{
    unsigned long long r;
    asm("mov.b64 %0, {%1, %1};" : "=l"(r) : "f"(x));
    return r;
}
__device__ __forceinline__ void unpack2(unsigned long long v, float& lo, float& hi)
{
    asm("mov.b64 {%0, %1}, %2;" : "=f"(lo), "=f"(hi) : "l"(v));
}
__device__ __forceinline__ unsigned ld_acq(const unsigned* p)
{
    unsigned v;
    asm volatile("ld.global.acquire.gpu.u32 %0, [%1];" : "=r"(v) : "l"(p) : "memory");
    return v;
}
__device__ __forceinline__ unsigned ld_rlx(const unsigned* p)
{
    unsigned v;
    asm volatile("ld.global.relaxed.gpu.u32 %0, [%1];" : "=r"(v) : "l"(p) : "memory");
    return v;
}
__device__ __forceinline__ void st_rel(unsigned* p, unsigned v)
{
    asm volatile("st.global.release.gpu.u32 [%0], %1;" :: "l"(p), "r"(v) : "memory");
}

// ---------------------------------------------------------------------------
// FFMA2 NT SGEMM (proven, R12): C[m][n] = sum_k A[m][k] * B[n][k]
// ---------------------------------------------------------------------------
__global__ __launch_bounds__(256) void sgemm_nt2(
    const float* __restrict__ A,
    const float* __restrict__ Bm,
    float* __restrict__ C,
    int M, int N, int K)
{
    __shared__ float As[16][128];
    __shared__ float Bs[16][128];

    const int tid = threadIdx.x;
    const int m0 = blockIdx.y * 128;
    const int n0 = blockIdx.x * 128;
    const int tx = tid & 15;
    const int ty = tid >> 4;

    unsigned long long acc[8][4];
#pragma unroll
    for (int i = 0; i < 8; i++)
#pragma unroll
        for (int j = 0; j < 4; j++) acc[i][j] = 0ull;

    for (int k0 = 0; k0 < K; k0 += 16) {
#pragma unroll
        for (int q = 0; q < 2; ++q) {
            int i = tid + q * 256;
            int m = i >> 2;
            int kq = (i & 3) * 4;
            float4 v = *(const float4*)(A + (long)(m0 + m) * K + k0 + kq);
            As[kq + 0][m] = v.x;
            As[kq + 1][m] = v.y;
            As[kq + 2][m] = v.z;
            As[kq + 3][m] = v.w;
        }
#pragma unroll
        for (int q = 0; q < 2; ++q) {
            int i = tid + q * 256;
            int n = i >> 2;
            int kq = (i & 3) * 4;
            float4 v = *(const float4*)(Bm + (long)(n0 + n) * K + k0 + kq);
            Bs[kq + 0][n] = v.x;
            Bs[kq + 1][n] = v.y;
            Bs[kq + 2][n] = v.z;
            Bs[kq + 3][n] = v.w;
        }
        __syncthreads();

#pragma unroll
        for (int k = 0; k < 16; ++k) {
            float a[8];
#pragma unroll
            for (int q = 0; q < 2; ++q)
                *(float4*)&a[q * 4] = *(const float4*)&As[k][ty * 8 + q * 4];
            ulonglong2 b01 = *(const ulonglong2*)&Bs[k][tx * 8];
            ulonglong2 b23 = *(const ulonglong2*)&Bs[k][tx * 8 + 4];
#pragma unroll
            for (int i = 0; i < 8; ++i) {
                unsigned long long ai = pack2(a[i]);
                ffma2(acc[i][0], ai, b01.x);
                ffma2(acc[i][1], ai, b01.y);
                ffma2(acc[i][2], ai, b23.x);
                ffma2(acc[i][3], ai, b23.y);
            }
        }
        __syncthreads();
    }

#pragma unroll
    for (int i = 0; i < 8; ++i) {
        float r[8];
#pragma unroll
        for (int j = 0; j < 4; ++j) unpack2(acc[i][j], r[2 * j], r[2 * j + 1]);
        float* dst = C + (long)(m0 + ty * 8 + i) * N + n0 + tx * 8;
        *(float4*)dst       = *(float4*)&r[0];
        *(float4*)(dst + 4) = *(float4*)&r[4];
    }
}

// ---------------------------------------------------------------------------
// Sequential recurrence v9: R13 + relaxed early flag read.
//
// Grid = 128 CTAs = 16 bt x 8 jt. 256 threads = 8 warps (k-split 64 each).
// Temporal 2-group phase shift. Per phase:
//   TOP: ld.relaxed of the NEXT phase's flag (no ordering, drains under kloop)
//   STS prefetched h -> hTw; kloop (fma-bound, 1024 cyc floor)
//   STS partials -> red
//   if flag was fresh: issue hx LDGs (control-dep ordering; release->L2 +
//   ldcg-from-L2 gives freshness); else mark pending
//   syncthreads; reduce+tanh+STG; syncthreads; st.release flag
//   pending (rare): sound acquire-poll + reload
// ---------------------------------------------------------------------------
#define NTHR     256
#define HTW_STR  272                       // 4*68 floats per (warp,group)
#define RED_FOFF (16 * HTW_STR)            // 4352 floats
#define SMEM_BYTES (RED_FOFF * 4 + 2 * 2048 * 8)   // 50176

__global__ __launch_bounds__(NTHR, 1) void rnn_seq9(
    const float* __restrict__ Wh,   // [NH][NH]
    const float* __restrict__ h0,   // [B][NH]
    float* __restrict__ hs)         // [B][T][NH]: pre in, h out (in place)
{
    extern __shared__ float sm[];

    const int tid  = threadIdx.x;
    const int wid  = tid >> 5;
    const int lane = tid & 31;

    const int jt  = blockIdx.x & 7;
    const int bt  = blockIdx.x >> 3;
    const int j0g = jt * 64;
    const int b0  = bt * 8;
    const int kw0 = wid * 64;

    // ---- Wh slice into registers (cols lane*2, lane*2+1; k = kw0..+64) ----
    unsigned long long W[64];
#pragma unroll
    for (int c = 0; c < 2; ++c) {
        const float* row = Wh + (size_t)(j0g + lane * 2 + c) * NH_ + kw0;
#pragma unroll
        for (int q = 0; q < 16; ++q) {
            ulonglong2 v = *(const ulonglong2*)(row + q * 4);
            W[c * 32 + 2 * q]     = v.x;
            W[c * 32 + 2 * q + 1] = v.y;
        }
    }

    // reload mapping: lane -> (batch rb, 8-float chunk f4)
    const int rb = lane >> 3;
    const int f4 = (lane & 7) * 8;
    // epilogue mapping
    const int eb = tid >> 6;   // 0..3
    const int ej = tid & 63;

    // ---- prologue: prefetch phase 0 (g=0, t=0) h from h0 ----
    float4 hx0, hx1;
    {
        const float* src = h0 + (size_t)(b0 + rb) * NH_ + kw0 + f4;
        hx0 = __ldcg((const float4*)src);
        hx1 = __ldcg((const float4*)(src + 4));
    }

    for (int p = 0; p < 2 * T_; ++p) {
        const int g = p & 1;
        const int t = p >> 1;
        unsigned* flags = &g_flag2[bt][g][0];
        float* hTw = sm + (wid * 2 + g) * HTW_STR;
        unsigned long long* red =
            (unsigned long long*)(sm + RED_FOFF) + (size_t)g * 2048;
        const int b0g = b0 + g * 4;

        // ---- EARLY relaxed read of the next phase's flag (non-blocking) ----
        const unsigned* f2p = nullptr;
        const float* nsrc = nullptr;
        unsigned vflag = 0;
        int t2 = 0;
        if (p + 1 < 2 * T_) {
            const int g2 = g ^ 1;
            t2 = (p + 1) >> 1;
            const int b0g2 = b0 + g2 * 4;
            if (t2 == 0) {
                nsrc = h0 + (size_t)(b0g2 + rb) * NH_ + kw0 + f4;
            } else {
                f2p = &g_flag2[bt][g2][0] + wid;
                vflag = ld_rlx(f2p);    // completes during the kloop
                nsrc = hs + ((size_t)(b0g2 + rb) * T_ + (t2 - 1)) * NH_ + kw0 + f4;
            }
        }

        // pre-activation for this phase (consumed at reduce)
        float pre = __ldcg(hs + ((size_t)(b0g + eb) * T_ + t) * NH_ + j0g + ej);

        // ---- STS prefetched h, then k-loop ----
        *(float4*)&hTw[rb * 68 + f4]     = hx0;
        *(float4*)&hTw[rb * 68 + f4 + 4] = hx1;
        __syncwarp();

        unsigned long long acc[4][2];
#pragma unroll
        for (int b = 0; b < 4; ++b) { acc[b][0] = 0ull; acc[b][1] = 0ull; }

#pragma unroll
        for (int b = 0; b < 4; ++b) {
            const float* hb = &hTw[b * 68];
#pragma unroll
            for (int q = 0; q < 16; ++q) {
                ulonglong2 va = *(const ulonglong2*)(hb + q * 4);
                ffma2(acc[b][0], va.x, W[2 * q]);
                ffma2(acc[b][0], va.y, W[2 * q + 1]);
                ffma2(acc[b][1], va.x, W[32 + 2 * q]);
                ffma2(acc[b][1], va.y, W[32 + 2 * q + 1]);
            }
        }

        // ---- stash partials (unaffected by any flag ordering) ----
#pragma unroll
        for (int b = 0; b < 4; ++b) {
            ulonglong2 v; v.x = acc[b][0]; v.y = acc[b][1];
            *(ulonglong2*)&red[(size_t)wid * 256 + b * 64 + lane * 2] = v;
        }

        // ---- speculative next-phase h load, gated by the (arrived) flag ----
        bool pending = false;
        if (p + 1 < 2 * T_) {
            if (f2p == nullptr || (vflag - (unsigned)t2) <= 1u) {
                hx0 = __ldcg((const float4*)nsrc);
                hx1 = __ldcg((const float4*)(nsrc + 4));
            } else {
                pending = true;
            }
        }

        __syncthreads();

        // ---- reduce 8 warps, fold k-pairs, add pre, tanh, publish ----
        {
            float s = pre;
#pragma unroll
            for (int w = 0; w < 8; ++w) {
                float lo, hi;
                unpack2(red[(size_t)w * 256 + eb * 64 + ej], lo, hi);
                s += lo + hi;
            }
            float hv = tanhf(s);
            hs[((size_t)(b0g + eb) * T_ + t) * NH_ + j0g + ej] = hv;
        }

        __syncthreads();
        if (tid == 0) st_rel(flags + jt, (unsigned)(t + 1));

        // ---- rare slow path: flag was stale at the relaxed read ----
        if (pending) {
            for (;;) {
                unsigned v = ld_acq(f2p);
                if ((v - (unsigned)t2) <= 1u) break;
                __nanosleep(20);
            }
            hx0 = __ldcg((const float4*)nsrc);
            hx1 = __ldcg((const float4*)(nsrc + 4));
        }
    }
}

// ---------------------------------------------------------------------------
// Launch: [sgemm2(pre), rnn_seq9, sgemm2(y)]
// ---------------------------------------------------------------------------
extern "C" void kernel_launch(void* const* d_in, const int* in_sizes, int n_in,
                              void* d_out, int out_size)
{
    const float* x  = (const float*)d_in[0];
    const float* h0 = (const float*)d_in[1];
    const float* Wi = (const float*)d_in[2];
    const float* Wh = (const float*)d_in[3];
    const float* Wy = (const float*)d_in[4];

    float* y  = (float*)d_out;
    float* hs = y + (size_t)B_ * T_ * NY_;

    // Phase 1: pre = x @ Wi^T -> hs region (scratch)
    {
        dim3 grid(NH_ / 128, (B_ * T_) / 128);
        sgemm_nt2<<<grid, 256>>>(x, Wi, hs, B_ * T_, NH_, NX_);
    }
    // Phase 2: sequential recurrence
    {
        cudaFuncSetAttribute(rnn_seq9,
                             cudaFuncAttributeMaxDynamicSharedMemorySize, SMEM_BYTES);
        rnn_seq9<<<128, NTHR, SMEM_BYTES>>>(Wh, h0, hs);
    }
    // Phase 3: y = hs @ Wy^T
    {
        dim3 grid(NY_ / 128, (B_ * T_) / 128);
        sgemm_nt2<<<grid, 256>>>(hs, Wy, y, B_ * T_, NY_, NH_);
    }
}

// round 15
// speedup vs baseline: 1.1626x; 1.1626x over previous
#include <cuda_runtime.h>
#include <math.h>
#include <stdint.h>

#define B_  128
#define T_  1024
#define NX_ 256
#define NH_ 512
#define NY_ 256

// Progress flags: g_flag2[bt][group][jt], row padded to 32 words (128B).
__device__ unsigned g_flag2[16][2][32];

// ---------------------------------------------------------------------------
// FFMA2 helpers
// ---------------------------------------------------------------------------
__device__ __forceinline__ void ffma2(unsigned long long& d,
                                      unsigned long long a, unsigned long long b)
{
    asm("fma.rn.f32x2 %0, %1, %2, %0;" : "+l"(d) : "l"(a), "l"(b));
}
__device__ __forceinline__ unsigned long long pack2(float x)
{
    unsigned long long r;
    asm("mov.b64 %0, {%1, %1};" : "=l"(r) : "f"(x));
    return r;
}
__device__ __forceinline__ void unpack2(unsigned long long v, float& lo, float& hi)
{
    asm("mov.b64 {%0, %1}, %2;" : "=f"(lo), "=f"(hi) : "l"(v));
}
__device__ __forceinline__ unsigned ld_acq(const unsigned* p)
{
    unsigned v;
    asm volatile("ld.global.acquire.gpu.u32 %0, [%1];" : "=r"(v) : "l"(p) : "memory");
    return v;
}
__device__ __forceinline__ unsigned ld_rlx(const unsigned* p)
{
    unsigned v;
    asm volatile("ld.global.relaxed.gpu.u32 %0, [%1];" : "=r"(v) : "l"(p) : "memory");
    return v;
}
__device__ __forceinline__ void st_rel(unsigned* p, unsigned v)
{
    asm volatile("st.global.release.gpu.u32 [%0], %1;" :: "l"(p), "r"(v) : "memory");
}

// ---------------------------------------------------------------------------
// FFMA2 NT SGEMM (proven, R12): C[m][n] = sum_k A[m][k] * B[n][k]
// ---------------------------------------------------------------------------
__global__ __launch_bounds__(256) void sgemm_nt2(
    const float* __restrict__ A,
    const float* __restrict__ Bm,
    float* __restrict__ C,
    int M, int N, int K)
{
    __shared__ float As[16][128];
    __shared__ float Bs[16][128];

    const int tid = threadIdx.x;
    const int m0 = blockIdx.y * 128;
    const int n0 = blockIdx.x * 128;
    const int tx = tid & 15;
    const int ty = tid >> 4;

    unsigned long long acc[8][4];
#pragma unroll
    for (int i = 0; i < 8; i++)
#pragma unroll
        for (int j = 0; j < 4; j++) acc[i][j] = 0ull;

    for (int k0 = 0; k0 < K; k0 += 16) {
#pragma unroll
        for (int q = 0; q < 2; ++q) {
            int i = tid + q * 256;
            int m = i >> 2;
            int kq = (i & 3) * 4;
            float4 v = *(const float4*)(A + (long)(m0 + m) * K + k0 + kq);
            As[kq + 0][m] = v.x;
            As[kq + 1][m] = v.y;
            As[kq + 2][m] = v.z;
            As[kq + 3][m] = v.w;
        }
#pragma unroll
        for (int q = 0; q < 2; ++q) {
            int i = tid + q * 256;
            int n = i >> 2;
            int kq = (i & 3) * 4;
            float4 v = *(const float4*)(Bm + (long)(n0 + n) * K + k0 + kq);
            Bs[kq + 0][n] = v.x;
            Bs[kq + 1][n] = v.y;
            Bs[kq + 2][n] = v.z;
            Bs[kq + 3][n] = v.w;
        }
        __syncthreads();

#pragma unroll
        for (int k = 0; k < 16; ++k) {
            float a[8];
#pragma unroll
            for (int q = 0; q < 2; ++q)
                *(float4*)&a[q * 4] = *(const float4*)&As[k][ty * 8 + q * 4];
            ulonglong2 b01 = *(const ulonglong2*)&Bs[k][tx * 8];
            ulonglong2 b23 = *(const ulonglong2*)&Bs[k][tx * 8 + 4];
#pragma unroll
            for (int i = 0; i < 8; ++i) {
                unsigned long long ai = pack2(a[i]);
                ffma2(acc[i][0], ai, b01.x);
                ffma2(acc[i][1], ai, b01.y);
                ffma2(acc[i][2], ai, b23.x);
                ffma2(acc[i][3], ai, b23.y);
            }
        }
        __syncthreads();
    }

#pragma unroll
    for (int i = 0; i < 8; ++i) {
        float r[8];
#pragma unroll
        for (int j = 0; j < 4; ++j) unpack2(acc[i][j], r[2 * j], r[2 * j + 1]);
        float* dst = C + (long)(m0 + ty * 8 + i) * N + n0 + tx * 8;
        *(float4*)dst       = *(float4*)&r[0];
        *(float4*)(dst + 4) = *(float4*)&r[4];
    }
}

// ---------------------------------------------------------------------------
// Sequential recurrence v10 = R13 structure, with the post-kloop flag read
// downgraded acquire -> relaxed + branch-gated hx loads (ordering applies
// only to the two LDGs, not to the partials/reduce path).
//
// Grid = 128 CTAs = 16 bt x 8 jt. 256 threads = 8 warps (k-split 64 each).
// Temporal 2-group phase shift (groups of 4 batches). Per phase:
//   STS prefetched h -> hTw; kloop (fma-bound);
//   relaxed read of next phase's flag (same point as R13's acquire);
//   fresh -> issue hx LDGs (drain under reduce/publish); stale -> pending;
//   STS partials; sync; reduce+tanh+STG; sync; st.release flag;
//   pending slow path: acquire-poll + reload (rare).
// ---------------------------------------------------------------------------
#define NTHR     256
#define HTW_STR  272                       // 4*68 floats per (warp,group)
#define RED_FOFF (16 * HTW_STR)            // 4352 floats
#define SMEM_BYTES (RED_FOFF * 4 + 2 * 2048 * 8)   // 50176

__global__ __launch_bounds__(NTHR, 1) void rnn_seq10(
    const float* __restrict__ Wh,   // [NH][NH]
    const float* __restrict__ h0,   // [B][NH]
    float* __restrict__ hs)         // [B][T][NH]: pre in, h out (in place)
{
    extern __shared__ float sm[];

    const int tid  = threadIdx.x;
    const int wid  = tid >> 5;
    const int lane = tid & 31;

    const int jt  = blockIdx.x & 7;
    const int bt  = blockIdx.x >> 3;
    const int j0g = jt * 64;
    const int b0  = bt * 8;
    const int kw0 = wid * 64;

    // ---- Wh slice into registers (cols lane*2, lane*2+1; k = kw0..+64) ----
    unsigned long long W[64];
#pragma unroll
    for (int c = 0; c < 2; ++c) {
        const float* row = Wh + (size_t)(j0g + lane * 2 + c) * NH_ + kw0;
#pragma unroll
        for (int q = 0; q < 16; ++q) {
            ulonglong2 v = *(const ulonglong2*)(row + q * 4);
            W[c * 32 + 2 * q]     = v.x;
            W[c * 32 + 2 * q + 1] = v.y;
        }
    }

    // reload mapping: lane -> (batch rb, 8-float chunk f4)
    const int rb = lane >> 3;
    const int f4 = (lane & 7) * 8;
    // epilogue mapping
    const int eb = tid >> 6;   // 0..3
    const int ej = tid & 63;

    // ---- prologue: prefetch phase 0 (g=0, t=0) h from h0 ----
    float4 hx0, hx1;
    {
        const float* src = h0 + (size_t)(b0 + rb) * NH_ + kw0 + f4;
        hx0 = __ldcg((const float4*)src);
        hx1 = __ldcg((const float4*)(src + 4));
    }

    for (int p = 0; p < 2 * T_; ++p) {
        const int g = p & 1;
        const int t = p >> 1;
        unsigned* flags = &g_flag2[bt][g][0];
        float* hTw = sm + (wid * 2 + g) * HTW_STR;
        unsigned long long* red =
            (unsigned long long*)(sm + RED_FOFF) + (size_t)g * 2048;
        const int b0g = b0 + g * 4;

        // pre-activation for this phase (consumed at reduce)
        float pre = __ldcg(hs + ((size_t)(b0g + eb) * T_ + t) * NH_ + j0g + ej);

        // ---- STS prefetched h, then k-loop ----
        *(float4*)&hTw[rb * 68 + f4]     = hx0;
        *(float4*)&hTw[rb * 68 + f4 + 4] = hx1;
        __syncwarp();

        unsigned long long acc[4][2];
#pragma unroll
        for (int b = 0; b < 4; ++b) { acc[b][0] = 0ull; acc[b][1] = 0ull; }

#pragma unroll
        for (int b = 0; b < 4; ++b) {
            const float* hb = &hTw[b * 68];
#pragma unroll
            for (int q = 0; q < 16; ++q) {
                ulonglong2 va = *(const ulonglong2*)(hb + q * 4);
                ffma2(acc[b][0], va.x, W[2 * q]);
                ffma2(acc[b][0], va.y, W[2 * q + 1]);
                ffma2(acc[b][1], va.x, W[32 + 2 * q]);
                ffma2(acc[b][1], va.y, W[32 + 2 * q + 1]);
            }
        }

        // ---- speculative next-phase prefetch (relaxed read, gated LDGs) ----
        const unsigned* f2p = nullptr;
        const float* nsrc = nullptr;
        bool pending = false;
        int t2 = 0;
        if (p + 1 < 2 * T_) {
            const int g2 = g ^ 1;
            t2 = (p + 1) >> 1;
            const int b0g2 = b0 + g2 * 4;
            if (t2 == 0) {
                nsrc = h0 + (size_t)(b0g2 + rb) * NH_ + kw0 + f4;
                hx0 = __ldcg((const float4*)nsrc);
                hx1 = __ldcg((const float4*)(nsrc + 4));
            } else {
                f2p = &g_flag2[bt][g2][0] + wid;
                unsigned vflag = ld_rlx(f2p);   // no ordering: stalls nothing
                nsrc = hs + ((size_t)(b0g2 + rb) * T_ + (t2 - 1)) * NH_ + kw0 + f4;
                if ((vflag - (unsigned)t2) <= 1u) {
                    // fresh: release->L2 + ldcg-from-L2 gives valid data
                    hx0 = __ldcg((const float4*)nsrc);
                    hx1 = __ldcg((const float4*)(nsrc + 4));
                } else {
                    pending = true;
                }
            }
        }

        // ---- stash partials, reduce, tanh, publish ----
#pragma unroll
        for (int b = 0; b < 4; ++b) {
            ulonglong2 v; v.x = acc[b][0]; v.y = acc[b][1];
            *(ulonglong2*)&red[(size_t)wid * 256 + b * 64 + lane * 2] = v;
        }
        __syncthreads();

        {
            float s = pre;
#pragma unroll
            for (int w = 0; w < 8; ++w) {
                float lo, hi;
                unpack2(red[(size_t)w * 256 + eb * 64 + ej], lo, hi);
                s += lo + hi;
            }
            float hv = tanhf(s);
            hs[((size_t)(b0g + eb) * T_ + t) * NH_ + j0g + ej] = hv;
        }

        __syncthreads();
        if (tid == 0) st_rel(flags + jt, (unsigned)(t + 1));

        // ---- rare slow path: flag was stale at the relaxed read ----
        if (pending) {
            for (;;) {
                unsigned v = ld_acq(f2p);
                if ((v - (unsigned)t2) <= 1u) break;
                __nanosleep(20);
            }
            hx0 = __ldcg((const float4*)nsrc);
            hx1 = __ldcg((const float4*)(nsrc + 4));
        }
    }
}

// ---------------------------------------------------------------------------
// Launch: [sgemm2(pre), rnn_seq10, sgemm2(y)]
// ---------------------------------------------------------------------------
extern "C" void kernel_launch(void* const* d_in, const int* in_sizes, int n_in,
                              void* d_out, int out_size)
{
    const float* x  = (const float*)d_in[0];
    const float* h0 = (const float*)d_in[1];
    const float* Wi = (const float*)d_in[2];
    const float* Wh = (const float*)d_in[3];
    const float* Wy = (const float*)d_in[4];

    float* y  = (float*)d_out;
    float* hs = y + (size_t)B_ * T_ * NY_;

    // Phase 1: pre = x @ Wi^T -> hs region (scratch)
    {
        dim3 grid(NH_ / 128, (B_ * T_) / 128);
        sgemm_nt2<<<grid, 256>>>(x, Wi, hs, B_ * T_, NH_, NX_);
    }
    // Phase 2: sequential recurrence
    {
        cudaFuncSetAttribute(rnn_seq10,
                             cudaFuncAttributeMaxDynamicSharedMemorySize, SMEM_BYTES);
        rnn_seq10<<<128, NTHR, SMEM_BYTES>>>(Wh, h0, hs);
    }
    // Phase 3: y = hs @ Wy^T
    {
        dim3 grid(NY_ / 128, (B_ * T_) / 128);
        sgemm_nt2<<<grid, 256>>>(hs, Wy, y, B_ * T_, NY_, NH_);
    }
}

// round 16
// speedup vs baseline: 1.4138x; 1.2161x over previous
#include <cuda_runtime.h>
#include <cuda_bf16.h>
#include <math.h>
#include <stdint.h>

#define B_  128
#define T_  1024
#define NX_ 256
#define NH_ 512
#define NY_ 256

// Progress flags: g_flag2[bt][group][jt], row padded to 32 words (128B).
__device__ unsigned g_flag2[16][2][32];

// ---------------------------------------------------------------------------
// FFMA2 / ordering helpers (seq kernel, unchanged from R15)
// ---------------------------------------------------------------------------
__device__ __forceinline__ void ffma2(unsigned long long& d,
                                      unsigned long long a, unsigned long long b)
{
    asm("fma.rn.f32x2 %0, %1, %2, %0;" : "+l"(d) : "l"(a), "l"(b));
}
__device__ __forceinline__ void unpack2(unsigned long long v, float& lo, float& hi)
{
    asm("mov.b64 {%0, %1}, %2;" : "=f"(lo), "=f"(hi) : "l"(v));
}
__device__ __forceinline__ unsigned ld_acq(const unsigned* p)
{
    unsigned v;
    asm volatile("ld.global.acquire.gpu.u32 %0, [%1];" : "=r"(v) : "l"(p) : "memory");
    return v;
}
__device__ __forceinline__ unsigned ld_rlx(const unsigned* p)
{
    unsigned v;
    asm volatile("ld.global.relaxed.gpu.u32 %0, [%1];" : "=r"(v) : "l"(p) : "memory");
    return v;
}
__device__ __forceinline__ void st_rel(unsigned* p, unsigned v)
{
    asm volatile("st.global.release.gpu.u32 [%0], %1;" :: "l"(p), "r"(v) : "memory");
}

// ---------------------------------------------------------------------------
// bf16 split helpers
// ---------------------------------------------------------------------------
__device__ __forceinline__ unsigned bf16_pair(float f0, float f1)
{
    unsigned u0 = __bfloat16_as_ushort(__float2bfloat16_rn(f0));
    unsigned u1 = __bfloat16_as_ushort(__float2bfloat16_rn(f1));
    return u0 | (u1 << 16);
}
// hi pair + residuals
__device__ __forceinline__ unsigned bf16_hi_pair(float f0, float f1,
                                                 float& r0, float& r1)
{
    __nv_bfloat16 h0 = __float2bfloat16_rn(f0);
    __nv_bfloat16 h1 = __float2bfloat16_rn(f1);
    r0 = f0 - __bfloat162float(h0);
    r1 = f1 - __bfloat162float(h1);
    return (unsigned)__bfloat16_as_ushort(h0) |
           ((unsigned)__bfloat16_as_ushort(h1) << 16);
}

__device__ __forceinline__ void mma_bf16(float& c0, float& c1, float& c2, float& c3,
    unsigned a0, unsigned a1, unsigned a2, unsigned a3, unsigned b0, unsigned b1)
{
    asm volatile(
        "mma.sync.aligned.m16n8k16.row.col.f32.bf16.bf16.f32 "
        "{%0,%1,%2,%3}, {%4,%5,%6,%7}, {%8,%9}, {%0,%1,%2,%3};"
        : "+f"(c0), "+f"(c1), "+f"(c2), "+f"(c3)
        : "r"(a0), "r"(a1), "r"(a2), "r"(a3), "r"(b0), "r"(b1));
}

// ---------------------------------------------------------------------------
// bf16-split tensor-core NT GEMM: C[m][n] = sum_k A[m][k] * B[n][k]
// 3-product split (hh + hl + lh); in-kernel conversion at tile load.
// CTA tile 128(m) x 64(n), BK=16, 256 threads = 8 warps (4m x 2n),
// warp tile 32x32 = 2(m16) x 4(n8) mma tiles. SMEM u32 stride 12
// (conflict-free fragment LDS: 12*g mod 32 distinct for g=0..7).
// ---------------------------------------------------------------------------
__global__ __launch_bounds__(256) void sgemm_bf16s(
    const float* __restrict__ A,
    const float* __restrict__ Bm,
    float* __restrict__ C,
    int M, int N, int K)
{
    __shared__ unsigned Ah[128 * 12];
    __shared__ unsigned Al[128 * 12];
    __shared__ unsigned Bh[64 * 12];
    __shared__ unsigned Bl[64 * 12];

    const int tid  = threadIdx.x;
    const int lane = tid & 31;
    const int wid  = tid >> 5;
    const int g    = lane >> 2;       // groupID 0..7
    const int t4   = lane & 3;        // threadID in group
    const int wm   = (wid & 3) * 32;  // warp m offset in tile
    const int wn   = (wid >> 2) * 32; // warp n offset in tile
    const long m0  = (long)blockIdx.y * 128;
    const int  n0  = blockIdx.x * 64;

    const int r8 = tid >> 3;          // 0..31
    const int c8 = tid & 7;           // float2 column 0..7

    float acc[2][4][4];
#pragma unroll
    for (int mt = 0; mt < 2; ++mt)
#pragma unroll
        for (int nt = 0; nt < 4; ++nt)
#pragma unroll
            for (int i = 0; i < 4; ++i) acc[mt][nt][i] = 0.0f;

    for (int kc = 0; kc < K; kc += 16) {
        // ---- A tile 128x16: fp32 -> (hi, lo) bf16 pairs ----
#pragma unroll
        for (int q = 0; q < 4; ++q) {
            int rr = r8 + q * 32;
            float2 v = *(const float2*)(A + (m0 + rr) * K + kc + c8 * 2);
            float r0, r1;
            unsigned h = bf16_hi_pair(v.x, v.y, r0, r1);
            Ah[rr * 12 + c8] = h;
            Al[rr * 12 + c8] = bf16_pair(r0, r1);
        }
        // ---- B tile 64x16 ----
#pragma unroll
        for (int q = 0; q < 2; ++q) {
            int rr = r8 + q * 32;
            float2 v = *(const float2*)(Bm + (long)(n0 + rr) * K + kc + c8 * 2);
            float r0, r1;
            unsigned h = bf16_hi_pair(v.x, v.y, r0, r1);
            Bh[rr * 12 + c8] = h;
            Bl[rr * 12 + c8] = bf16_pair(r0, r1);
        }
        __syncthreads();

        // ---- fragment loads (conflict-free) ----
        unsigned ah[2][4], al[2][4], bh[4][2], bl[4][2];
#pragma unroll
        for (int mt = 0; mt < 2; ++mt) {
            int rb = (wm + mt * 16 + g) * 12;
            ah[mt][0] = Ah[rb + t4];
            ah[mt][1] = Ah[rb + 96 + t4];       // +8 rows
            ah[mt][2] = Ah[rb + t4 + 4];
            ah[mt][3] = Ah[rb + 96 + t4 + 4];
            al[mt][0] = Al[rb + t4];
            al[mt][1] = Al[rb + 96 + t4];
            al[mt][2] = Al[rb + t4 + 4];
            al[mt][3] = Al[rb + 96 + t4 + 4];
        }
#pragma unroll
        for (int nt = 0; nt < 4; ++nt) {
            int rb = (wn + nt * 8 + g) * 12;
            bh[nt][0] = Bh[rb + t4];
            bh[nt][1] = Bh[rb + t4 + 4];
            bl[nt][0] = Bl[rb + t4];
            bl[nt][1] = Bl[rb + t4 + 4];
        }

        // ---- 3 products, product-outer (dependent HMMAs 8 apart) ----
#pragma unroll
        for (int mt = 0; mt < 2; ++mt)
#pragma unroll
            for (int nt = 0; nt < 4; ++nt)
                mma_bf16(acc[mt][nt][0], acc[mt][nt][1], acc[mt][nt][2], acc[mt][nt][3],
                         ah[mt][0], ah[mt][1], ah[mt][2], ah[mt][3],
                         bh[nt][0], bh[nt][1]);
#pragma unroll
        for (int mt = 0; mt < 2; ++mt)
#pragma unroll
            for (int nt = 0; nt < 4; ++nt)
                mma_bf16(acc[mt][nt][0], acc[mt][nt][1], acc[mt][nt][2], acc[mt][nt][3],
                         ah[mt][0], ah[mt][1], ah[mt][2], ah[mt][3],
                         bl[nt][0], bl[nt][1]);
#pragma unroll
        for (int mt = 0; mt < 2; ++mt)
#pragma unroll
            for (int nt = 0; nt < 4; ++nt)
                mma_bf16(acc[mt][nt][0], acc[mt][nt][1], acc[mt][nt][2], acc[mt][nt][3],
                         al[mt][0], al[mt][1], al[mt][2], al[mt][3],
                         bh[nt][0], bh[nt][1]);

        __syncthreads();
    }

    // ---- epilogue ----
#pragma unroll
    for (int mt = 0; mt < 2; ++mt) {
#pragma unroll
        for (int nt = 0; nt < 4; ++nt) {
            long row = m0 + wm + mt * 16 + g;
            int  col = n0 + wn + nt * 8 + t4 * 2;
            *(float2*)(C + row * N + col) =
                make_float2(acc[mt][nt][0], acc[mt][nt][1]);
            *(float2*)(C + (row + 8) * N + col) =
                make_float2(acc[mt][nt][2], acc[mt][nt][3]);
        }
    }
}

// ---------------------------------------------------------------------------
// Sequential recurrence v10 (FROZEN — R15 best, 4586us): temporal 2-group
// phase shift, register-resident Wh, relaxed post-kloop flag read with
// branch-gated speculative h prefetch, acquire-poll slow path.
// ---------------------------------------------------------------------------
#define NTHR     256
#define HTW_STR  272
#define RED_FOFF (16 * HTW_STR)
#define SMEM_BYTES (RED_FOFF * 4 + 2 * 2048 * 8)   // 50176

__global__ __launch_bounds__(NTHR, 1) void rnn_seq10(
    const float* __restrict__ Wh,
    const float* __restrict__ h0,
    float* __restrict__ hs)
{
    extern __shared__ float sm[];

    const int tid  = threadIdx.x;
    const int wid  = tid >> 5;
    const int lane = tid & 31;

    const int jt  = blockIdx.x & 7;
    const int bt  = blockIdx.x >> 3;
    const int j0g = jt * 64;
    const int b0  = bt * 8;
    const int kw0 = wid * 64;

    unsigned long long W[64];
#pragma unroll
    for (int c = 0; c < 2; ++c) {
        const float* row = Wh + (size_t)(j0g + lane * 2 + c) * NH_ + kw0;
#pragma unroll
        for (int q = 0; q < 16; ++q) {
            ulonglong2 v = *(const ulonglong2*)(row + q * 4);
            W[c * 32 + 2 * q]     = v.x;
            W[c * 32 + 2 * q + 1] = v.y;
        }
    }

    const int rb = lane >> 3;
    const int f4 = (lane & 7) * 8;
    const int eb = tid >> 6;
    const int ej = tid & 63;

    float4 hx0, hx1;
    {
        const float* src = h0 + (size_t)(b0 + rb) * NH_ + kw0 + f4;
        hx0 = __ldcg((const float4*)src);
        hx1 = __ldcg((const float4*)(src + 4));
    }

    for (int p = 0; p < 2 * T_; ++p) {
        const int g = p & 1;
        const int t = p >> 1;
        unsigned* flags = &g_flag2[bt][g][0];
        float* hTw = sm + (wid * 2 + g) * HTW_STR;
        unsigned long long* red =
            (unsigned long long*)(sm + RED_FOFF) + (size_t)g * 2048;
        const int b0g = b0 + g * 4;

        float pre = __ldcg(hs + ((size_t)(b0g + eb) * T_ + t) * NH_ + j0g + ej);

        *(float4*)&hTw[rb * 68 + f4]     = hx0;
        *(float4*)&hTw[rb * 68 + f4 + 4] = hx1;
        __syncwarp();

        unsigned long long acc[4][2];
#pragma unroll
        for (int b = 0; b < 4; ++b) { acc[b][0] = 0ull; acc[b][1] = 0ull; }

#pragma unroll
        for (int b = 0; b < 4; ++b) {
            const float* hb = &hTw[b * 68];
#pragma unroll
            for (int q = 0; q < 16; ++q) {
                ulonglong2 va = *(const ulonglong2*)(hb + q * 4);
                ffma2(acc[b][0], va.x, W[2 * q]);
                ffma2(acc[b][0], va.y, W[2 * q + 1]);
                ffma2(acc[b][1], va.x, W[32 + 2 * q]);
                ffma2(acc[b][1], va.y, W[32 + 2 * q + 1]);
            }
        }

        const unsigned* f2p = nullptr;
        const float* nsrc = nullptr;
        bool pending = false;
        int t2 = 0;
        if (p + 1 < 2 * T_) {
            const int g2 = g ^ 1;
            t2 = (p + 1) >> 1;
            const int b0g2 = b0 + g2 * 4;
            if (t2 == 0) {
                nsrc = h0 + (size_t)(b0g2 + rb) * NH_ + kw0 + f4;
                hx0 = __ldcg((const float4*)nsrc);
                hx1 = __ldcg((const float4*)(nsrc + 4));
            } else {
                f2p = &g_flag2[bt][g2][0] + wid;
                unsigned vflag = ld_rlx(f2p);
                nsrc = hs + ((size_t)(b0g2 + rb) * T_ + (t2 - 1)) * NH_ + kw0 + f4;
                if ((vflag - (unsigned)t2) <= 1u) {
                    hx0 = __ldcg((const float4*)nsrc);
                    hx1 = __ldcg((const float4*)(nsrc + 4));
                } else {
                    pending = true;
                }
            }
        }

#pragma unroll
        for (int b = 0; b < 4; ++b) {
            ulonglong2 v; v.x = acc[b][0]; v.y = acc[b][1];
            *(ulonglong2*)&red[(size_t)wid * 256 + b * 64 + lane * 2] = v;
        }
        __syncthreads();

        {
            float s = pre;
#pragma unroll
            for (int w = 0; w < 8; ++w) {
                float lo, hi;
                unpack2(red[(size_t)w * 256 + eb * 64 + ej], lo, hi);
                s += lo + hi;
            }
            float hv = tanhf(s);
            hs[((size_t)(b0g + eb) * T_ + t) * NH_ + j0g + ej] = hv;
        }

        __syncthreads();
        if (tid == 0) st_rel(flags + jt, (unsigned)(t + 1));

        if (pending) {
            for (;;) {
                unsigned v = ld_acq(f2p);
                if ((v - (unsigned)t2) <= 1u) break;
                __nanosleep(20);
            }
            hx0 = __ldcg((const float4*)nsrc);
            hx1 = __ldcg((const float4*)(nsrc + 4));
        }
    }
}

// ---------------------------------------------------------------------------
// Launch: [sgemm_bf16s(pre), rnn_seq10, sgemm_bf16s(y)]
// ---------------------------------------------------------------------------
extern "C" void kernel_launch(void* const* d_in, const int* in_sizes, int n_in,
                              void* d_out, int out_size)
{
    const float* x  = (const float*)d_in[0];
    const float* h0 = (const float*)d_in[1];
    const float* Wi = (const float*)d_in[2];
    const float* Wh = (const float*)d_in[3];
    const float* Wy = (const float*)d_in[4];

    float* y  = (float*)d_out;
    float* hs = y + (size_t)B_ * T_ * NY_;

    // Phase 1: pre = x @ Wi^T -> hs region (scratch)
    {
        dim3 grid(NH_ / 64, (B_ * T_) / 128);
        sgemm_bf16s<<<grid, 256>>>(x, Wi, hs, B_ * T_, NH_, NX_);
    }
    // Phase 2: sequential recurrence (frozen R15 best)
    {
        cudaFuncSetAttribute(rnn_seq10,
                             cudaFuncAttributeMaxDynamicSharedMemorySize, SMEM_BYTES);
        rnn_seq10<<<128, NTHR, SMEM_BYTES>>>(Wh, h0, hs);
    }
    // Phase 3: y = hs @ Wy^T
    {
        dim3 grid(NY_ / 64, (B_ * T_) / 128);
        sgemm_bf16s<<<grid, 256>>>(hs, Wy, y, B_ * T_, NY_, NH_);
    }
}